// round 10
// baseline (speedup 1.0000x reference)
#include <cuda_runtime.h>
#include <cstddef>
#include <cstdint>
#include <math_constants.h>

#define B_DIM 4096
#define K_DIM 64
#define D_DIM 512
#define N_AGENTS 64
#define NEG_INF -1e9f
#define THREADS 512
#define NWARP 16
#define GRID 148
#define NBUF 4
#define CHUNK_ROWS 16
#define CHUNK_BYTES (CHUNK_ROWS * D_DIM * 4)      // 32 KB
#define CHUNK_FLOATS (CHUNK_ROWS * D_DIM)
#define STAGE_OFF (NBUF * CHUNK_BYTES)            // 131072
#define MBAR_OFF  (STAGE_OFF + NWARP * D_DIM * 4) // 163840
#define SMEM_TOTAL (MBAR_OFF + 128)

__device__ __forceinline__ uint32_t smem_u32(const void* p) {
    return (uint32_t)__cvta_generic_to_shared(p);
}
__device__ __forceinline__ void mbar_init(uint32_t a, uint32_t cnt) {
    asm volatile("mbarrier.init.shared.b64 [%0], %1;" :: "r"(a), "r"(cnt) : "memory");
}
__device__ __forceinline__ void mbar_expect_tx(uint32_t a, uint32_t bytes) {
    asm volatile("mbarrier.arrive.expect_tx.shared.b64 _, [%0], %1;" :: "r"(a), "r"(bytes) : "memory");
}
__device__ __forceinline__ void mbar_arrive(uint32_t a) {
    asm volatile("mbarrier.arrive.shared.b64 _, [%0];" :: "r"(a) : "memory");
}
__device__ __forceinline__ void mbar_wait(uint32_t a, uint32_t parity) {
    while (true) {
        uint32_t done;
        asm volatile(
            "{\n\t.reg .pred p;\n\t"
            "mbarrier.try_wait.parity.acquire.cta.shared::cta.b64 p, [%1], %2, 0x989680;\n\t"
            "selp.b32 %0, 1, 0, p;\n\t}"
            : "=r"(done) : "r"(a), "r"(parity) : "memory");
        if (done) break;
    }
}
__device__ __forceinline__ void bulk_copy(uint32_t dst_smem, const void* src, uint32_t bytes, uint32_t mbar) {
    asm volatile(
        "cp.async.bulk.shared::cluster.global.mbarrier::complete_tx::bytes [%0], [%1], %2, [%3];"
        :: "r"(dst_smem), "l"(src), "r"(bytes), "r"(mbar) : "memory");
}

__global__ __launch_bounds__(THREADS, 1)
void block_diag_agg_kernel(const float* __restrict__ h,
                           const float* __restrict__ keys,
                           const int* __restrict__ sigma,
                           float* __restrict__ out) {
    extern __shared__ __align__(128) char smem[];
    __shared__ float s_m[NWARP];
    __shared__ float s_s[NWARP];
    __shared__ float s_fac[NWARP];

    const int tid  = threadIdx.x;
    const int warp = tid >> 5;
    const int lane = tid & 31;
    const int bid  = blockIdx.x;

    const uint32_t smem_base = smem_u32(smem);
    const uint32_t full_bar  = smem_base + MBAR_OFF;        // 4 x 8 B
    const uint32_t empty_bar = smem_base + MBAR_OFF + 32;   // 4 x 8 B

    const int ntiles = (B_DIM - bid + GRID - 1) / GRID;
    const int total_chunks = ntiles * 4;

    if (tid == 0) {
        #pragma unroll
        for (int s = 0; s < NBUF; s++) {
            mbar_init(full_bar  + s * 8, 1);       // producer's expect_tx arrive
            mbar_init(empty_bar + s * 8, NWARP);   // one arrive per consumer warp
        }
    }
    __syncthreads();

    // ---- Prologue: fill the pipeline with the first NBUF chunks ----
    if (tid == 0) {
        #pragma unroll
        for (int g = 0; g < NBUF; g++) {           // total_chunks >= 4 always
            const int t = g >> 2, c = g & 3;
            const float* src = h + (size_t)(bid + t * GRID) * (K_DIM * D_DIM) + c * CHUNK_FLOATS;
            mbar_expect_tx(full_bar + c * 8, CHUNK_BYTES);
            bulk_copy(smem_base + c * CHUNK_BYTES, src, CHUNK_BYTES, full_bar + c * 8);
        }
    }

    float* stage = (float*)(smem + STAGE_OFF);

    for (int t = 0; t < ntiles; t++) {
        const int b = bid + t * GRID;
        const int*   sb = sigma + (size_t)b * K_DIM;
        const uint32_t p = t & 1;                  // full/empty parity for this tile

        float m = -CUDART_INF_F;
        float s = 0.0f;
        float4 acc0 = make_float4(0.f, 0.f, 0.f, 0.f);
        float4 acc1 = make_float4(0.f, 0.f, 0.f, 0.f);
        float4 acc2 = make_float4(0.f, 0.f, 0.f, 0.f);
        float4 acc3 = make_float4(0.f, 0.f, 0.f, 0.f);

        #pragma unroll
        for (int c = 0; c < 4; c++) {
            const int g = t * 4 + c;
            mbar_wait(full_bar + c * 8, p);

            // warp w consumes buffer row w (global slot k = 16c + w)
            const int k = c * CHUNK_ROWS + warp;
            const int sid    = __ldg(&sb[k]);
            const bool valid = (sid < N_AGENTS);
            const float4* hrow = (const float4*)(smem + c * CHUNK_BYTES + warp * (D_DIM * 4));
            const float4* krow = (const float4*)(keys + (size_t)(valid ? sid : 0) * D_DIM);

            float4 hv0 = hrow[lane +  0];
            float4 hv1 = hrow[lane + 32];
            float4 hv2 = hrow[lane + 64];
            float4 hv3 = hrow[lane + 96];
            float4 kv0 = __ldg(&krow[lane +  0]);
            float4 kv1 = __ldg(&krow[lane + 32]);
            float4 kv2 = __ldg(&krow[lane + 64]);
            float4 kv3 = __ldg(&krow[lane + 96]);

            float dot = 0.0f;
            dot = fmaf(hv0.x, kv0.x, dot); dot = fmaf(hv0.y, kv0.y, dot);
            dot = fmaf(hv0.z, kv0.z, dot); dot = fmaf(hv0.w, kv0.w, dot);
            dot = fmaf(hv1.x, kv1.x, dot); dot = fmaf(hv1.y, kv1.y, dot);
            dot = fmaf(hv1.z, kv1.z, dot); dot = fmaf(hv1.w, kv1.w, dot);
            dot = fmaf(hv2.x, kv2.x, dot); dot = fmaf(hv2.y, kv2.y, dot);
            dot = fmaf(hv2.z, kv2.z, dot); dot = fmaf(hv2.w, kv2.w, dot);
            dot = fmaf(hv3.x, kv3.x, dot); dot = fmaf(hv3.y, kv3.y, dot);
            dot = fmaf(hv3.z, kv3.z, dot); dot = fmaf(hv3.w, kv3.w, dot);

            #pragma unroll
            for (int off = 16; off > 0; off >>= 1)
                dot += __shfl_xor_sync(0xFFFFFFFFu, dot, off);

            const float logit = valid ? dot : NEG_INF;
            const float m_new = fmaxf(m, logit);
            const float scale = __expf(m - m_new);     // first iter: exp(-inf)=0
            const float pw    = __expf(logit - m_new);
            s = fmaf(s, scale, pw);
            m = m_new;

            acc0.x = fmaf(acc0.x, scale, pw * hv0.x);
            acc0.y = fmaf(acc0.y, scale, pw * hv0.y);
            acc0.z = fmaf(acc0.z, scale, pw * hv0.z);
            acc0.w = fmaf(acc0.w, scale, pw * hv0.w);
            acc1.x = fmaf(acc1.x, scale, pw * hv1.x);
            acc1.y = fmaf(acc1.y, scale, pw * hv1.y);
            acc1.z = fmaf(acc1.z, scale, pw * hv1.z);
            acc1.w = fmaf(acc1.w, scale, pw * hv1.w);
            acc2.x = fmaf(acc2.x, scale, pw * hv2.x);
            acc2.y = fmaf(acc2.y, scale, pw * hv2.y);
            acc2.z = fmaf(acc2.z, scale, pw * hv2.z);
            acc2.w = fmaf(acc2.w, scale, pw * hv2.w);
            acc3.x = fmaf(acc3.x, scale, pw * hv3.x);
            acc3.y = fmaf(acc3.y, scale, pw * hv3.y);
            acc3.z = fmaf(acc3.z, scale, pw * hv3.z);
            acc3.w = fmaf(acc3.w, scale, pw * hv3.w);

            __syncwarp();
            if (lane == 0) mbar_arrive(empty_bar + c * 8);

            // refill this slot with chunk g+NBUF once every warp drained it
            if (tid == 0 && g + NBUF < total_chunks) {
                mbar_wait(empty_bar + c * 8, p);
                const int gn = g + NBUF, tn = gn >> 2, cn = gn & 3;
                const float* src = h + (size_t)(bid + tn * GRID) * (K_DIM * D_DIM) + cn * CHUNK_FLOATS;
                mbar_expect_tx(full_bar + cn * 8, CHUNK_BYTES);
                bulk_copy(smem_base + cn * CHUNK_BYTES, src, CHUNK_BYTES, full_bar + cn * 8);
            }
        }

        // ---- Epilogue: merge 16 per-warp softmax states, stage, reduce, store.
        //      Overlaps with TMA streaming of the next tile's chunks. ----
        if (lane == 0) { s_m[warp] = m; s_s[warp] = s; }
        __syncthreads();

        if (warp == 0) {
            float mw = (lane < NWARP) ? s_m[lane] : -CUDART_INF_F;
            float sw = (lane < NWARP) ? s_s[lane] : 0.0f;
            float mg = mw;
            #pragma unroll
            for (int off = 16; off > 0; off >>= 1)
                mg = fmaxf(mg, __shfl_xor_sync(0xFFFFFFFFu, mg, off));
            float e = __expf(mw - mg);
            float S = e * sw;
            #pragma unroll
            for (int off = 16; off > 0; off >>= 1)
                S += __shfl_xor_sync(0xFFFFFFFFu, S, off);
            if (lane < NWARP) s_fac[lane] = e / S;
        }
        __syncthreads();

        const float f = s_fac[warp];
        float4* stp = (float4*)(stage + warp * D_DIM);
        stp[lane +  0] = make_float4(acc0.x * f, acc0.y * f, acc0.z * f, acc0.w * f);
        stp[lane + 32] = make_float4(acc1.x * f, acc1.y * f, acc1.z * f, acc1.w * f);
        stp[lane + 64] = make_float4(acc2.x * f, acc2.y * f, acc2.z * f, acc2.w * f);
        stp[lane + 96] = make_float4(acc3.x * f, acc3.y * f, acc3.z * f, acc3.w * f);
        __syncthreads();

        float outv = 0.0f;
        #pragma unroll
        for (int w = 0; w < NWARP; w++)
            outv += stage[w * D_DIM + tid];
        out[(size_t)b * D_DIM + tid] = outv;
    }
}

extern "C" void kernel_launch(void* const* d_in, const int* in_sizes, int n_in,
                              void* d_out, int out_size) {
    const float* h     = (const float*)d_in[0];
    const float* keys  = (const float*)d_in[1];
    const int*   sigma = (const int*)d_in[2];
    float*       out   = (float*)d_out;

    cudaFuncSetAttribute(block_diag_agg_kernel,
                         cudaFuncAttributeMaxDynamicSharedMemorySize, SMEM_TOTAL);
    block_diag_agg_kernel<<<GRID, THREADS, SMEM_TOTAL>>>(h, keys, sigma, out);
}

// round 11
// speedup vs baseline: 1.1740x; 1.1740x over previous
#include <cuda_runtime.h>
#include <cstddef>

#define B_DIM 4096
#define K_DIM 64
#define D_DIM 512
#define N_AGENTS 64
#define NEG_INF -1e9f
#define THREADS 512
#define PF_DIST 296                    // prefetch for the CTA ~1 wave-slot ahead

__device__ __forceinline__ float ldcs_f(const float* p) {
    float v;
    asm volatile("ld.global.cs.f32 %0, [%1];" : "=f"(v) : "l"(p));
    return v;
}
__device__ __forceinline__ float4 ldcs_f4(const float4* p) {
    float4 v;
    asm volatile("ld.global.cs.v4.f32 {%0,%1,%2,%3}, [%4];"
                 : "=f"(v.x), "=f"(v.y), "=f"(v.z), "=f"(v.w) : "l"(p));
    return v;
}

__global__ __launch_bounds__(THREADS, 3)
void block_diag_agg_kernel(const float* __restrict__ h,
                           const float* __restrict__ keys,
                           const int* __restrict__ sigma,
                           float* __restrict__ out) {
    __shared__ float  s_logits[K_DIM];
    __shared__ float  s_alpha[K_DIM];
    __shared__ float4 s_part[4][D_DIM / 4];   // 8 KB partial pooling sums

    const int b    = blockIdx.x;
    const int tid  = threadIdx.x;
    const int warp = tid >> 5;
    const int lane = tid & 31;

    const float* hb = h + (size_t)b * (K_DIM * D_DIM);
    const int*   sb = sigma + (size_t)b * K_DIM;

    // Prefetch target: tile of the CTA that will occupy this slot next.
    const int bpre = b + PF_DIST;
    const char* pfb = (const char*)(h + (size_t)bpre * (K_DIM * D_DIM));
    const bool do_pf = (bpre < B_DIM) && (tid < 256);   // warps 0-7, uniform per warp

    // ---- Phase 1: per-slot dot products. 16 warps x 4 k-slots.
    //      Each iteration also drip-feeds 256 prefetch lines (32 KB) of the
    //      next-wave tile into L2 with evict_last priority. ----
    #pragma unroll
    for (int i = 0; i < 4; i++) {
        if (do_pf) {
            const char* pf = pfb + ((size_t)i * 256 + tid) * 128;
            asm volatile("prefetch.global.L2::evict_last [%0];" :: "l"(pf));
        }

        const int k = warp * 4 + i;
        const int sid    = sb[k];
        const bool valid = (sid < N_AGENTS);
        const float4* hrow = (const float4*)(hb + (size_t)k * D_DIM);
        const float4* krow = (const float4*)(keys + (size_t)(valid ? sid : 0) * D_DIM);

        float acc = 0.0f;
        #pragma unroll
        for (int j = 0; j < 4; j++) {
            const int idx = lane + 32 * j;            // 0..127 float4 per row
            float4 hv = __ldcg(&hrow[idx]);           // keep in L2 for phase 3
            float4 kv = __ldg(&krow[idx]);            // keys L1-resident
            acc = fmaf(hv.x, kv.x, acc);
            acc = fmaf(hv.y, kv.y, acc);
            acc = fmaf(hv.z, kv.z, acc);
            acc = fmaf(hv.w, kv.w, acc);
        }
        #pragma unroll
        for (int off = 16; off > 0; off >>= 1)
            acc += __shfl_xor_sync(0xFFFFFFFFu, acc, off);
        if (lane == 0)
            s_logits[k] = valid ? acc : NEG_INF;
    }
    __syncthreads();

    // ---- Phase 2: softmax over K=64 (warp 0 only) ----
    if (warp == 0) {
        float l0 = s_logits[lane];
        float l1 = s_logits[lane + 32];
        float m = fmaxf(l0, l1);
        #pragma unroll
        for (int off = 16; off > 0; off >>= 1)
            m = fmaxf(m, __shfl_xor_sync(0xFFFFFFFFu, m, off));
        float e0 = __expf(l0 - m);
        float e1 = __expf(l1 - m);
        float s = e0 + e1;
        #pragma unroll
        for (int off = 16; off > 0; off >>= 1)
            s += __shfl_xor_sync(0xFFFFFFFFu, s, off);
        float inv = 1.0f / s;
        s_alpha[lane]      = e0 * inv;
        s_alpha[lane + 32] = e1 * inv;
    }
    __syncthreads();

    // ---- Phase 3: vectorized pooling, last touch of this tile.
    //      __ldcs marks lines evict-first so the prefetch stream reclaims
    //      dead lines instead of live ones. ----
    {
        const int g  = tid >> 7;        // 0..3 (16 k-slots each)
        const int d4 = tid & 127;       // float4 index over 512 dims
        const float4* hrow4 = (const float4*)hb + (size_t)(g * 16) * (D_DIM / 4) + d4;
        const float*  ap    = &s_alpha[g * 16];

        float4 acc = make_float4(0.f, 0.f, 0.f, 0.f);
        #pragma unroll
        for (int k = 0; k < 16; k++) {
            const float a   = ap[k];
            const float4 hv = ldcs_f4(hrow4 + (size_t)k * (D_DIM / 4));
            acc.x = fmaf(a, hv.x, acc.x);
            acc.y = fmaf(a, hv.y, acc.y);
            acc.z = fmaf(a, hv.z, acc.z);
            acc.w = fmaf(a, hv.w, acc.w);
        }
        s_part[g][d4] = acc;
    }
    __syncthreads();

    // ---- Final 4-way reduction + store ----
    {
        const float* p = (const float*)s_part;        // [4][512] floats
        float v = p[tid] + p[D_DIM + tid] + p[2 * D_DIM + tid] + p[3 * D_DIM + tid];
        out[(size_t)b * D_DIM + tid] = v;
    }
}

extern "C" void kernel_launch(void* const* d_in, const int* in_sizes, int n_in,
                              void* d_out, int out_size) {
    const float* h     = (const float*)d_in[0];
    const float* keys  = (const float*)d_in[1];
    const int*   sigma = (const int*)d_in[2];
    float*       out   = (float*)d_out;

    block_diag_agg_kernel<<<B_DIM, THREADS>>>(h, keys, sigma, out);
}

// round 12
// speedup vs baseline: 1.2470x; 1.0622x over previous
#include <cuda_runtime.h>
#include <cstddef>
#include <math_constants.h>

#define B_DIM 4096
#define K_DIM 64
#define D_DIM 512
#define N_AGENTS 64
#define NEG_INF -1e9f
#define THREADS 512
#define GRID 296
#define NUNITS (GRID * 2)      // 592 independent phase units
#define GWARPS 8               // warps per group

__device__ __forceinline__ void gbar(int id) {
    asm volatile("bar.sync %0, 256;" :: "r"(id) : "memory");
}

__global__ __launch_bounds__(THREADS, 2)
void block_diag_agg_kernel(const float* __restrict__ h,
                           const float* __restrict__ keys,
                           const int* __restrict__ sigma,
                           float* __restrict__ out) {
    __shared__ float s_m[2][GWARPS];
    __shared__ float s_s[2][GWARPS];
    __shared__ float s_fac[2][GWARPS];
    __shared__ float s_stage[2][GWARPS][D_DIM];   // 32 KB

    const int tid  = threadIdx.x;
    const int g    = tid >> 8;          // group 0/1
    const int gtid = tid & 255;         // 0..255 within group
    const int lw   = gtid >> 5;         // warp within group, 0..7
    const int lane = tid & 31;
    const int bar0 = 1 + g;             // private named barrier id (1 or 2)
    const int unit = blockIdx.x * 2 + g;

    for (int b = unit; b < B_DIM; b += NUNITS) {
        const float* hb = h + (size_t)b * (K_DIM * D_DIM);
        const int*   sb = sigma + (size_t)b * K_DIM;

        // ---- Mainloop: per-warp online softmax over 8 owned k-slots.
        //      h read once from DRAM; continuous load stream per unit. ----
        float m = -CUDART_INF_F;
        float s = 0.0f;
        float4 acc0 = make_float4(0.f, 0.f, 0.f, 0.f);
        float4 acc1 = make_float4(0.f, 0.f, 0.f, 0.f);
        float4 acc2 = make_float4(0.f, 0.f, 0.f, 0.f);
        float4 acc3 = make_float4(0.f, 0.f, 0.f, 0.f);

        #pragma unroll
        for (int i = 0; i < 8; i++) {
            const int k = lw * 8 + i;
            const int sid    = __ldg(&sb[k]);
            const bool valid = (sid < N_AGENTS);
            const float4* hrow = (const float4*)(hb + (size_t)k * D_DIM);
            const float4* krow = (const float4*)(keys + (size_t)(valid ? sid : 0) * D_DIM);

            float4 hv0 = __ldcg(&hrow[lane +  0]);
            float4 hv1 = __ldcg(&hrow[lane + 32]);
            float4 hv2 = __ldcg(&hrow[lane + 64]);
            float4 hv3 = __ldcg(&hrow[lane + 96]);
            float4 kv0 = __ldg(&krow[lane +  0]);
            float4 kv1 = __ldg(&krow[lane + 32]);
            float4 kv2 = __ldg(&krow[lane + 64]);
            float4 kv3 = __ldg(&krow[lane + 96]);

            float dot = 0.0f;
            dot = fmaf(hv0.x, kv0.x, dot); dot = fmaf(hv0.y, kv0.y, dot);
            dot = fmaf(hv0.z, kv0.z, dot); dot = fmaf(hv0.w, kv0.w, dot);
            dot = fmaf(hv1.x, kv1.x, dot); dot = fmaf(hv1.y, kv1.y, dot);
            dot = fmaf(hv1.z, kv1.z, dot); dot = fmaf(hv1.w, kv1.w, dot);
            dot = fmaf(hv2.x, kv2.x, dot); dot = fmaf(hv2.y, kv2.y, dot);
            dot = fmaf(hv2.z, kv2.z, dot); dot = fmaf(hv2.w, kv2.w, dot);
            dot = fmaf(hv3.x, kv3.x, dot); dot = fmaf(hv3.y, kv3.y, dot);
            dot = fmaf(hv3.z, kv3.z, dot); dot = fmaf(hv3.w, kv3.w, dot);

            #pragma unroll
            for (int off = 16; off > 0; off >>= 1)
                dot += __shfl_xor_sync(0xFFFFFFFFu, dot, off);

            const float logit = valid ? dot : NEG_INF;
            const float m_new = fmaxf(m, logit);
            const float scale = __expf(m - m_new);     // iter 0: exp(-inf)=0
            const float pw    = __expf(logit - m_new);
            s = fmaf(s, scale, pw);
            m = m_new;

            acc0.x = fmaf(acc0.x, scale, pw * hv0.x);
            acc0.y = fmaf(acc0.y, scale, pw * hv0.y);
            acc0.z = fmaf(acc0.z, scale, pw * hv0.z);
            acc0.w = fmaf(acc0.w, scale, pw * hv0.w);
            acc1.x = fmaf(acc1.x, scale, pw * hv1.x);
            acc1.y = fmaf(acc1.y, scale, pw * hv1.y);
            acc1.z = fmaf(acc1.z, scale, pw * hv1.z);
            acc1.w = fmaf(acc1.w, scale, pw * hv1.w);
            acc2.x = fmaf(acc2.x, scale, pw * hv2.x);
            acc2.y = fmaf(acc2.y, scale, pw * hv2.y);
            acc2.z = fmaf(acc2.z, scale, pw * hv2.z);
            acc2.w = fmaf(acc2.w, scale, pw * hv2.w);
            acc3.x = fmaf(acc3.x, scale, pw * hv3.x);
            acc3.y = fmaf(acc3.y, scale, pw * hv3.y);
            acc3.z = fmaf(acc3.z, scale, pw * hv3.z);
            acc3.w = fmaf(acc3.w, scale, pw * hv3.w);
        }

        if (lane == 0) { s_m[g][lw] = m; s_s[g][lw] = s; }
        gbar(bar0);

        // ---- Merge the 8 per-warp softmax states (warp 0 of the group) ----
        if (lw == 0) {
            float mw = (lane < GWARPS) ? s_m[g][lane] : -CUDART_INF_F;
            float sw = (lane < GWARPS) ? s_s[g][lane] : 0.0f;
            float mg = mw;
            #pragma unroll
            for (int off = 16; off > 0; off >>= 1)
                mg = fmaxf(mg, __shfl_xor_sync(0xFFFFFFFFu, mg, off));
            float e = __expf(mw - mg);                 // inactive lanes: 0
            float S = e * sw;
            #pragma unroll
            for (int off = 16; off > 0; off >>= 1)
                S += __shfl_xor_sync(0xFFFFFFFFu, S, off);
            if (lane < GWARPS) s_fac[g][lane] = e / S;
        }
        gbar(bar0);

        // ---- Stage scaled per-warp partials ----
        const float f = s_fac[g][lw];
        float4* stp = (float4*)&s_stage[g][lw][0];
        stp[lane +  0] = make_float4(acc0.x * f, acc0.y * f, acc0.z * f, acc0.w * f);
        stp[lane + 32] = make_float4(acc1.x * f, acc1.y * f, acc1.z * f, acc1.w * f);
        stp[lane + 64] = make_float4(acc2.x * f, acc2.y * f, acc2.z * f, acc2.w * f);
        stp[lane + 96] = make_float4(acc3.x * f, acc3.y * f, acc3.z * f, acc3.w * f);
        gbar(bar0);

        // ---- Tree-sum across the 8 warps; thread gtid owns dims gtid, gtid+256 ----
        float v0 = 0.0f, v1 = 0.0f;
        #pragma unroll
        for (int w = 0; w < GWARPS; w++) {
            v0 += s_stage[g][w][gtid];
            v1 += s_stage[g][w][gtid + 256];
        }
        out[(size_t)b * D_DIM + gtid]       = v0;
        out[(size_t)b * D_DIM + gtid + 256] = v1;

        gbar(bar0);   // protect s_stage / s_m / s_s against next-tile overwrite
    }
}

extern "C" void kernel_launch(void* const* d_in, const int* in_sizes, int n_in,
                              void* d_out, int out_size) {
    const float* h     = (const float*)d_in[0];
    const float* keys  = (const float*)d_in[1];
    const int*   sigma = (const int*)d_in[2];
    float*       out   = (float*)d_out;

    block_diag_agg_kernel<<<GRID, THREADS>>>(h, keys, sigma, out);
}

// round 13
// speedup vs baseline: 1.4399x; 1.1546x over previous
#include <cuda_runtime.h>
#include <cstddef>
#include <cstdint>
#include <math_constants.h>

#define B_DIM 4096
#define K_DIM 64
#define D_DIM 512
#define N_AGENTS 64
#define NEG_INF -1e9f
#define THREADS 256
#define NWARP 8
#define GRID 296
#define NBUF 4
#define CROWS 8
#define CBYTES (CROWS * D_DIM * 4)            // 16 KB
#define CFLOATS (CROWS * D_DIM)
#define STAGE_OFF (NBUF * CBYTES)             // 65536
#define MBAR_OFF (STAGE_OFF + NWARP * D_DIM * 4)  // 81920
#define SMEM_TOTAL (MBAR_OFF + 64)

__device__ __forceinline__ uint32_t smem_u32(const void* p) {
    return (uint32_t)__cvta_generic_to_shared(p);
}
__device__ __forceinline__ void mbar_init(uint32_t a, uint32_t cnt) {
    asm volatile("mbarrier.init.shared.b64 [%0], %1;" :: "r"(a), "r"(cnt) : "memory");
}
__device__ __forceinline__ void mbar_expect_tx(uint32_t a, uint32_t bytes) {
    asm volatile("mbarrier.arrive.expect_tx.shared.b64 _, [%0], %1;" :: "r"(a), "r"(bytes) : "memory");
}
__device__ __forceinline__ void mbar_wait(uint32_t a, uint32_t parity) {
    while (true) {
        uint32_t done;
        asm volatile(
            "{\n\t.reg .pred p;\n\t"
            "mbarrier.try_wait.parity.acquire.cta.shared::cta.b64 p, [%1], %2, 0x989680;\n\t"
            "selp.b32 %0, 1, 0, p;\n\t}"
            : "=r"(done) : "r"(a), "r"(parity) : "memory");
        if (done) break;
    }
}
__device__ __forceinline__ void bulk_copy(uint32_t dst, const void* src, uint32_t bytes, uint32_t mbar) {
    asm volatile(
        "cp.async.bulk.shared::cluster.global.mbarrier::complete_tx::bytes [%0], [%1], %2, [%3];"
        :: "r"(dst), "l"(src), "r"(bytes), "r"(mbar) : "memory");
}

__global__ __launch_bounds__(THREADS, 2)
void block_diag_agg_kernel(const float* __restrict__ h,
                           const float* __restrict__ keys,
                           const int* __restrict__ sigma,
                           float* __restrict__ out) {
    extern __shared__ __align__(128) char smem[];
    __shared__ float s_m[NWARP];
    __shared__ float s_s[NWARP];
    __shared__ float s_fac[NWARP];

    const int tid  = threadIdx.x;
    const int warp = tid >> 5;
    const int lane = tid & 31;
    const int bid  = blockIdx.x;

    const uint32_t sb32     = smem_u32(smem);
    const uint32_t full_bar = sb32 + MBAR_OFF;    // 4 x 8 B

    const int ntiles = (B_DIM - bid + GRID - 1) / GRID;   // >= 13
    const int total  = ntiles * 8;                         // chunks in this CTA's stream

    if (tid == 0) {
        #pragma unroll
        for (int s = 0; s < NBUF; s++) mbar_init(full_bar + s * 8, 1);
    }
    __syncthreads();

    // ---- Prologue: queue the first NBUF chunks to the TMA engine ----
    if (tid == 0) {
        #pragma unroll
        for (int g = 0; g < NBUF; g++) {                   // all within tile 0
            const float* src = h + (size_t)bid * (K_DIM * D_DIM) + g * CFLOATS;
            mbar_expect_tx(full_bar + g * 8, CBYTES);
            bulk_copy(sb32 + g * CBYTES, src, CBYTES, full_bar + g * 8);
        }
    }

    float* stage = (float*)(smem + STAGE_OFF);

    for (int t = 0; t < ntiles; t++) {
        const int b   = bid + t * GRID;
        const int* sg = sigma + (size_t)b * K_DIM;

        float m = -CUDART_INF_F;
        float s = 0.0f;
        float4 acc0 = make_float4(0.f, 0.f, 0.f, 0.f);
        float4 acc1 = make_float4(0.f, 0.f, 0.f, 0.f);
        float4 acc2 = make_float4(0.f, 0.f, 0.f, 0.f);
        float4 acc3 = make_float4(0.f, 0.f, 0.f, 0.f);

        #pragma unroll
        for (int c = 0; c < 8; c++) {
            const int g   = t * 8 + c;
            const int buf = g & 3;
            mbar_wait(full_bar + buf * 8, (g >> 2) & 1);

            // warp w consumes row w of this chunk: global slot k = 8c + w
            const int k = c * CROWS + warp;
            const int sid    = __ldg(&sg[k]);
            const bool valid = (sid < N_AGENTS);
            const float4* hrow = (const float4*)(smem + buf * CBYTES + warp * (D_DIM * 4));
            const float4* krow = (const float4*)(keys + (size_t)(valid ? sid : 0) * D_DIM);

            float4 hv0 = hrow[lane +  0];
            float4 hv1 = hrow[lane + 32];
            float4 hv2 = hrow[lane + 64];
            float4 hv3 = hrow[lane + 96];
            float4 kv0 = __ldg(&krow[lane +  0]);
            float4 kv1 = __ldg(&krow[lane + 32]);
            float4 kv2 = __ldg(&krow[lane + 64]);
            float4 kv3 = __ldg(&krow[lane + 96]);

            float dot = 0.0f;
            dot = fmaf(hv0.x, kv0.x, dot); dot = fmaf(hv0.y, kv0.y, dot);
            dot = fmaf(hv0.z, kv0.z, dot); dot = fmaf(hv0.w, kv0.w, dot);
            dot = fmaf(hv1.x, kv1.x, dot); dot = fmaf(hv1.y, kv1.y, dot);
            dot = fmaf(hv1.z, kv1.z, dot); dot = fmaf(hv1.w, kv1.w, dot);
            dot = fmaf(hv2.x, kv2.x, dot); dot = fmaf(hv2.y, kv2.y, dot);
            dot = fmaf(hv2.z, kv2.z, dot); dot = fmaf(hv2.w, kv2.w, dot);
            dot = fmaf(hv3.x, kv3.x, dot); dot = fmaf(hv3.y, kv3.y, dot);
            dot = fmaf(hv3.z, kv3.z, dot); dot = fmaf(hv3.w, kv3.w, dot);

            #pragma unroll
            for (int off = 16; off > 0; off >>= 1)
                dot += __shfl_xor_sync(0xFFFFFFFFu, dot, off);

            const float logit = valid ? dot : NEG_INF;
            const float m_new = fmaxf(m, logit);
            const float scale = __expf(m - m_new);     // iter 0: exp(-inf)=0
            const float pw    = __expf(logit - m_new);
            s = fmaf(s, scale, pw);
            m = m_new;

            acc0.x = fmaf(acc0.x, scale, pw * hv0.x);
            acc0.y = fmaf(acc0.y, scale, pw * hv0.y);
            acc0.z = fmaf(acc0.z, scale, pw * hv0.z);
            acc0.w = fmaf(acc0.w, scale, pw * hv0.w);
            acc1.x = fmaf(acc1.x, scale, pw * hv1.x);
            acc1.y = fmaf(acc1.y, scale, pw * hv1.y);
            acc1.z = fmaf(acc1.z, scale, pw * hv1.z);
            acc1.w = fmaf(acc1.w, scale, pw * hv1.w);
            acc2.x = fmaf(acc2.x, scale, pw * hv2.x);
            acc2.y = fmaf(acc2.y, scale, pw * hv2.y);
            acc2.z = fmaf(acc2.z, scale, pw * hv2.z);
            acc2.w = fmaf(acc2.w, scale, pw * hv2.w);
            acc3.x = fmaf(acc3.x, scale, pw * hv3.x);
            acc3.y = fmaf(acc3.y, scale, pw * hv3.y);
            acc3.z = fmaf(acc3.z, scale, pw * hv3.z);
            acc3.w = fmaf(acc3.w, scale, pw * hv3.w);

            __syncthreads();   // all warps done with this buffer

            // refill buffer with chunk g+NBUF; engine keeps ~3 chunks queued
            if (tid == 0 && g + NBUF < total) {
                const int gn = g + NBUF, tn = gn >> 3, cn = gn & 7;
                const float* src = h + (size_t)(bid + tn * GRID) * (K_DIM * D_DIM) + cn * CFLOATS;
                mbar_expect_tx(full_bar + buf * 8, CBYTES);
                bulk_copy(sb32 + buf * CBYTES, src, CBYTES, full_bar + buf * 8);
            }
        }

        // ---- Epilogue (overlaps the already-queued TMA of the next tile) ----
        if (lane == 0) { s_m[warp] = m; s_s[warp] = s; }
        __syncthreads();

        if (warp == 0) {
            float mw = (lane < NWARP) ? s_m[lane] : -CUDART_INF_F;
            float sw = (lane < NWARP) ? s_s[lane] : 0.0f;
            float mg = mw;
            #pragma unroll
            for (int off = 16; off > 0; off >>= 1)
                mg = fmaxf(mg, __shfl_xor_sync(0xFFFFFFFFu, mg, off));
            float e = __expf(mw - mg);                 // inactive lanes: 0
            float S = e * sw;
            #pragma unroll
            for (int off = 16; off > 0; off >>= 1)
                S += __shfl_xor_sync(0xFFFFFFFFu, S, off);
            if (lane < NWARP) s_fac[lane] = e / S;
        }
        __syncthreads();

        const float f = s_fac[warp];
        float4* stp = (float4*)(stage + warp * D_DIM);
        stp[lane +  0] = make_float4(acc0.x * f, acc0.y * f, acc0.z * f, acc0.w * f);
        stp[lane + 32] = make_float4(acc1.x * f, acc1.y * f, acc1.z * f, acc1.w * f);
        stp[lane + 64] = make_float4(acc2.x * f, acc2.y * f, acc2.z * f, acc2.w * f);
        stp[lane + 96] = make_float4(acc3.x * f, acc3.y * f, acc3.z * f, acc3.w * f);
        __syncthreads();

        float v0 = 0.0f, v1 = 0.0f;
        #pragma unroll
        for (int w = 0; w < NWARP; w++) {
            v0 += stage[w * D_DIM + tid];
            v1 += stage[w * D_DIM + tid + 256];
        }
        out[(size_t)b * D_DIM + tid]       = v0;
        out[(size_t)b * D_DIM + tid + 256] = v1;

        __syncthreads();   // protect stage/s_m/s_s before next tile reuses them
    }
}

extern "C" void kernel_launch(void* const* d_in, const int* in_sizes, int n_in,
                              void* d_out, int out_size) {
    const float* h     = (const float*)d_in[0];
    const float* keys  = (const float*)d_in[1];
    const int*   sigma = (const int*)d_in[2];
    float*       out   = (float*)d_out;

    cudaFuncSetAttribute(block_diag_agg_kernel,
                         cudaFuncAttributeMaxDynamicSharedMemorySize, SMEM_TOTAL);
    block_diag_agg_kernel<<<GRID, THREADS, SMEM_TOTAL>>>(h, keys, sigma, out);
}